// round 1
// baseline (speedup 1.0000x reference)
#include <cuda_runtime.h>
#include <math.h>

#define BB 128
#define TT 1024
#define DD 512
#define HH 512

// ---------------- scratch (no allocations allowed) ----------------
__device__ float g_xp[(size_t)TT * BB * HH];   // [t][b][h], 256 MB
__device__ float g_h[2][BB * HH];              // ping-pong hidden state
__device__ unsigned g_ctr[8 * 32];             // per m-group barrier counter (128B apart)
__device__ unsigned g_gen[8 * 32];             // per m-group generation (monotonic)

// ---------------- f32x2 helpers ----------------
__device__ __forceinline__ unsigned long long ffma2(unsigned long long a,
                                                    unsigned long long b,
                                                    unsigned long long c) {
    unsigned long long d;
    asm("fma.rn.f32x2 %0, %1, %2, %3;" : "=l"(d) : "l"(a), "l"(b), "l"(c));
    return d;
}
__device__ __forceinline__ unsigned long long pack2(float x, float y) {
    unsigned long long d;
    asm("mov.b64 %0, {%1, %2};" : "=l"(d) : "f"(x), "f"(y));
    return d;
}
__device__ __forceinline__ void unpack2(unsigned long long v, float& x, float& y) {
    asm("mov.b64 {%0, %1}, %2;" : "=f"(x), "=f"(y) : "l"(v));
}

// =====================================================================
// Phase 1: xp[t][b][:] = x[b][t][:] @ W_ih + bias
// M = B*T = 131072 (row m = b*T + t), N = H = 512, K = D = 512
// 128x128 CTA tile, 256 threads, 8x8 microtile, f32x2 accumulators.
// grid = (4, 1024)
// =====================================================================
__global__ void __launch_bounds__(256) xp_gemm_kernel(
        const float* __restrict__ x, const float* __restrict__ Wih,
        const float* __restrict__ bias) {
    __shared__ float As[16][128];   // [k][m] (transposed)
    __shared__ float Bs[16][128];   // [k][n]

    const int tid = threadIdx.x;
    const int tx = tid & 15;        // n-group
    const int ty = tid >> 4;        // m-group
    const int m0 = blockIdx.y * 128;
    const int n0 = blockIdx.x * 128;

    unsigned long long acc[8][4];
#pragma unroll
    for (int i = 0; i < 8; i++)
#pragma unroll
        for (int j = 0; j < 4; j++) acc[i][j] = 0ull;

    for (int k0 = 0; k0 < DD; k0 += 16) {
        // load A tile (128 rows x 16 k), transposed into As[k][m]
#pragma unroll
        for (int q = 0; q < 2; q++) {
            int i = tid + q * 256;          // 0..511 float4 slots
            int row = i >> 2;
            int kc = (i & 3) * 4;
            float4 av = *(const float4*)&x[(size_t)(m0 + row) * DD + k0 + kc];
            As[kc + 0][row] = av.x;
            As[kc + 1][row] = av.y;
            As[kc + 2][row] = av.z;
            As[kc + 3][row] = av.w;
        }
        // load B tile (16 k x 128 n)
#pragma unroll
        for (int q = 0; q < 2; q++) {
            int i = tid + q * 256;
            int kr = i >> 5;
            int nc = (i & 31) * 4;
            float4 bv = *(const float4*)&Wih[(size_t)(k0 + kr) * HH + n0 + nc];
            *(float4*)&Bs[kr][nc] = bv;
        }
        __syncthreads();

#pragma unroll
        for (int kk = 0; kk < 16; kk++) {
            float4 a0 = *(const float4*)&As[kk][ty * 8];
            float4 a1 = *(const float4*)&As[kk][ty * 8 + 4];
            const unsigned long long* bp =
                (const unsigned long long*)&Bs[kk][tx * 8];
            unsigned long long b0 = bp[0], b1 = bp[1], b2 = bp[2], b3 = bp[3];
            float a[8] = {a0.x, a0.y, a0.z, a0.w, a1.x, a1.y, a1.z, a1.w};
#pragma unroll
            for (int i = 0; i < 8; i++) {
                unsigned long long ap = pack2(a[i], a[i]);
                acc[i][0] = ffma2(ap, b0, acc[i][0]);
                acc[i][1] = ffma2(ap, b1, acc[i][1]);
                acc[i][2] = ffma2(ap, b2, acc[i][2]);
                acc[i][3] = ffma2(ap, b3, acc[i][3]);
            }
        }
        __syncthreads();
    }

    // epilogue: add bias, scatter rows to [t][b][h] layout
    float4 bv0 = *(const float4*)&bias[n0 + tx * 8];
    float4 bv1 = *(const float4*)&bias[n0 + tx * 8 + 4];
    float bb8[8] = {bv0.x, bv0.y, bv0.z, bv0.w, bv1.x, bv1.y, bv1.z, bv1.w};
#pragma unroll
    for (int i = 0; i < 8; i++) {
        int mrow = m0 + ty * 8 + i;
        int b_ = mrow >> 10;       // / T
        int t_ = mrow & 1023;      // % T
        float f[8];
        unpack2(acc[i][0], f[0], f[1]);
        unpack2(acc[i][1], f[2], f[3]);
        unpack2(acc[i][2], f[4], f[5]);
        unpack2(acc[i][3], f[6], f[7]);
#pragma unroll
        for (int j = 0; j < 8; j++) f[j] += bb8[j];
        float* dst = &g_xp[((size_t)t_ * BB + b_) * HH + n0 + tx * 8];
        *(float4*)&dst[0] = make_float4(f[0], f[1], f[2], f[3]);
        *(float4*)&dst[4] = make_float4(f[4], f[5], f[6], f[7]);
    }
}

// =====================================================================
// Phase 2: recurrence. 128 CTAs = 8 m-groups (16 batch rows each)
//                           x 16 n-groups (32 cols each).
// W_hh slice (512x32) resident in smem for all 1024 steps.
// Sync only within the 16-CTA m-group (batch rows are independent).
// =====================================================================
#define HSP 516   // padded hs row length (floats) to avoid bank conflicts

__global__ void __launch_bounds__(256) rnn_steps_kernel(
        const float* __restrict__ Whh, float* __restrict__ out) {
    extern __shared__ float smem[];
    float* Ws = smem;                 // [512][32]
    float* hs = smem + 512 * 32;      // [16][HSP]

    const int tid = threadIdx.x;
    const int mg = blockIdx.x >> 4;   // 0..7
    const int ng = blockIdx.x & 15;   // 0..15
    const int row0 = mg * 16;
    const int col0 = ng * 32;

    // load W slice once: 512 x 32 floats
    for (int i = tid; i < 512 * 8; i += 256) {   // float4 count = 4096
        int k = i >> 3;
        int c4 = (i & 7) * 4;
        float4 v = *(const float4*)&Whh[(size_t)k * HH + col0 + c4];
        *(float4*)&Ws[k * 32 + c4] = v;
    }

    // thread tile mapping: 8 warps arranged 2(m) x 4(n) over 16x32 tile,
    // warp tile 8 rows x 8 cols, each lane one (row, col-pair)
    const int warp = tid >> 5, lane = tid & 31;
    const int R = (warp >> 2) * 8 + (lane >> 2);   // 0..15 (tile row)
    const int P = (warp & 3) * 4 + (lane & 3);     // 0..15 (pair index)
    const int gr = row0 + R;
    const int gc = col0 + 2 * P;

    unsigned* ctr = &g_ctr[mg * 32];
    volatile unsigned* gen = &g_gen[mg * 32];

    const float* hrow = &hs[R * HSP];
    const unsigned long long* wp = (const unsigned long long*)Ws + P;  // [k][16]

    for (int t = 0; t < TT; t++) {
        const float* hin = g_h[t & 1];
        if (t > 0) {
            // cooperative load of this group's 16 h rows (bypass L1: cross-SM data)
#pragma unroll
            for (int q = 0; q < 8; q++) {
                int i = tid + q * 256;          // 0..2047 float4 slots
                int r = i >> 7;                 // 128 float4 per row
                int c4 = (i & 127) * 4;
                float4 v = __ldcg((const float4*)&hin[(size_t)(row0 + r) * HH + c4]);
                *(float4*)&hs[r * HSP + c4] = v;
            }
        }
        __syncthreads();

        float2 xp = *(const float2*)&g_xp[((size_t)t * BB + gr) * HH + gc];

        float ax, ay;
        if (t > 0) {
            unsigned long long acc0 = 0ull, acc1 = 0ull;
#pragma unroll 4
            for (int k = 0; k < HH; k += 4) {
                float4 hq = *(const float4*)&hrow[k];
                acc0 = ffma2(pack2(hq.x, hq.x), wp[(k + 0) * 16], acc0);
                acc1 = ffma2(pack2(hq.y, hq.y), wp[(k + 1) * 16], acc1);
                acc0 = ffma2(pack2(hq.z, hq.z), wp[(k + 2) * 16], acc0);
                acc1 = ffma2(pack2(hq.w, hq.w), wp[(k + 3) * 16], acc1);
            }
            float a0x, a0y, a1x, a1y;
            unpack2(acc0, a0x, a0y);
            unpack2(acc1, a1x, a1y);
            ax = xp.x + a0x + a1x;
            ay = xp.y + a0y + a1y;
        } else {
            ax = xp.x;
            ay = xp.y;
        }
        float2 hv;
        hv.x = tanhf(ax);
        hv.y = tanhf(ay);

        float* hout = g_h[(t + 1) & 1];
        *(float2*)&hout[(size_t)gr * HH + gc] = hv;
        if (t == TT - 1) *(float2*)&out[(size_t)gr * HH + gc] = hv;

        // ---- m-group barrier (16 CTAs) ----
        __threadfence();
        __syncthreads();
        if (tid == 0) {
            unsigned g = *gen;                 // read generation BEFORE arriving
            unsigned tk = atomicAdd(ctr, 1u);
            if (tk == 15u) {
                *(volatile unsigned*)ctr = 0u;
                __threadfence();
                atomicAdd((unsigned*)gen, 1u); // release
            } else {
                while (*gen == g) { }          // spin on L2
            }
            __threadfence();                   // acquire
        }
        __syncthreads();
    }
}

// =====================================================================
extern "C" void kernel_launch(void* const* d_in, const int* in_sizes, int n_in,
                              void* d_out, int out_size) {
    const float* x    = (const float*)d_in[0];
    const float* Wih  = (const float*)d_in[1];
    const float* Whh  = (const float*)d_in[2];
    const float* bias = (const float*)d_in[3];
    float* out = (float*)d_out;

    const int smem2 = (512 * 32 + 16 * HSP) * (int)sizeof(float);  // ~98.5 KB
    cudaFuncSetAttribute(rnn_steps_kernel,
                         cudaFuncAttributeMaxDynamicSharedMemorySize, smem2);

    dim3 g1(HH / 128, (BB * TT) / 128);   // (4, 1024)
    xp_gemm_kernel<<<g1, 256>>>(x, Wih, bias);
    rnn_steps_kernel<<<128, 256, smem2>>>(Whh, out);
}

// round 3
// speedup vs baseline: 1.0265x; 1.0265x over previous
#include <cuda_runtime.h>
#include <math.h>

#define BB 128
#define TT 1024
#define DD 512
#define HH 512

// ---------------- scratch (no allocations allowed) ----------------
__device__ float g_xp[(size_t)TT * BB * HH];   // [t][b][h], 256 MB
__device__ float g_h[2][BB * HH];              // ping-pong hidden state
__device__ unsigned g_ctr[8 * 32];             // per m-group barrier counter (128B apart)
__device__ unsigned g_gen[8 * 32];             // per m-group generation (monotonic)

// ---------------- f32x2 helpers ----------------
__device__ __forceinline__ unsigned long long ffma2(unsigned long long a,
                                                    unsigned long long b,
                                                    unsigned long long c) {
    unsigned long long d;
    asm("fma.rn.f32x2 %0, %1, %2, %3;" : "=l"(d) : "l"(a), "l"(b), "l"(c));
    return d;
}
__device__ __forceinline__ unsigned long long pack2(float x, float y) {
    unsigned long long d;
    asm("mov.b64 %0, {%1, %2};" : "=l"(d) : "f"(x), "f"(y));
    return d;
}
__device__ __forceinline__ void unpack2(unsigned long long v, float& x, float& y) {
    asm("mov.b64 {%0, %1}, %2;" : "=f"(x), "=f"(y) : "l"(v));
}

// =====================================================================
// Phase 1: xp[t][b][:] = x[b][t][:] @ W_ih + bias
// =====================================================================
__global__ void __launch_bounds__(256) xp_gemm_kernel(
        const float* __restrict__ x, const float* __restrict__ Wih,
        const float* __restrict__ bias) {
    __shared__ float As[16][128];   // [k][m] (transposed)
    __shared__ float Bs[16][128];   // [k][n]

    const int tid = threadIdx.x;
    const int tx = tid & 15;        // n-group
    const int ty = tid >> 4;        // m-group
    const int m0 = blockIdx.y * 128;
    const int n0 = blockIdx.x * 128;

    unsigned long long acc[8][4];
#pragma unroll
    for (int i = 0; i < 8; i++)
#pragma unroll
        for (int j = 0; j < 4; j++) acc[i][j] = 0ull;

    for (int k0 = 0; k0 < DD; k0 += 16) {
#pragma unroll
        for (int q = 0; q < 2; q++) {
            int i = tid + q * 256;
            int row = i >> 2;
            int kc = (i & 3) * 4;
            float4 av = *(const float4*)&x[(size_t)(m0 + row) * DD + k0 + kc];
            As[kc + 0][row] = av.x;
            As[kc + 1][row] = av.y;
            As[kc + 2][row] = av.z;
            As[kc + 3][row] = av.w;
        }
#pragma unroll
        for (int q = 0; q < 2; q++) {
            int i = tid + q * 256;
            int kr = i >> 5;
            int nc = (i & 31) * 4;
            float4 bv = *(const float4*)&Wih[(size_t)(k0 + kr) * HH + n0 + nc];
            *(float4*)&Bs[kr][nc] = bv;
        }
        __syncthreads();

#pragma unroll
        for (int kk = 0; kk < 16; kk++) {
            float4 a0 = *(const float4*)&As[kk][ty * 8];
            float4 a1 = *(const float4*)&As[kk][ty * 8 + 4];
            const unsigned long long* bp =
                (const unsigned long long*)&Bs[kk][tx * 8];
            unsigned long long b0 = bp[0], b1 = bp[1], b2 = bp[2], b3 = bp[3];
            float a[8] = {a0.x, a0.y, a0.z, a0.w, a1.x, a1.y, a1.z, a1.w};
#pragma unroll
            for (int i = 0; i < 8; i++) {
                unsigned long long ap = pack2(a[i], a[i]);
                acc[i][0] = ffma2(ap, b0, acc[i][0]);
                acc[i][1] = ffma2(ap, b1, acc[i][1]);
                acc[i][2] = ffma2(ap, b2, acc[i][2]);
                acc[i][3] = ffma2(ap, b3, acc[i][3]);
            }
        }
        __syncthreads();
    }

    float4 bv0 = *(const float4*)&bias[n0 + tx * 8];
    float4 bv1 = *(const float4*)&bias[n0 + tx * 8 + 4];
    float bb8[8] = {bv0.x, bv0.y, bv0.z, bv0.w, bv1.x, bv1.y, bv1.z, bv1.w};
#pragma unroll
    for (int i = 0; i < 8; i++) {
        int mrow = m0 + ty * 8 + i;
        int b_ = mrow >> 10;
        int t_ = mrow & 1023;
        float f[8];
        unpack2(acc[i][0], f[0], f[1]);
        unpack2(acc[i][1], f[2], f[3]);
        unpack2(acc[i][2], f[4], f[5]);
        unpack2(acc[i][3], f[6], f[7]);
#pragma unroll
        for (int j = 0; j < 8; j++) f[j] += bb8[j];
        float* dst = &g_xp[((size_t)t_ * BB + b_) * HH + n0 + tx * 8];
        *(float4*)&dst[0] = make_float4(f[0], f[1], f[2], f[3]);
        *(float4*)&dst[4] = make_float4(f[4], f[5], f[6], f[7]);
    }
}

// =====================================================================
// Phase 2 v2 (FIXED): dot-product f32x2 recurrence.
// 128 CTAs = 8 m-groups (16 rows) x 16 n-groups (32 cols), 256 thr.
// Wt[q*32 + c] = float4( Whh[4q..4q+3][col0+c] ).
// ulonglong2 index == float4 index (16B each): col c0 at quad q is
// wp[q*32] (NOT q*16 — that was the R2 bug).
// =====================================================================
#define HSTRIDE 129   // float4 per smem h row (row offset = 4R banks mod 32 -> conflict-free)

__global__ void __launch_bounds__(256) rnn_steps_kernel(
        const float* __restrict__ Whh, float* __restrict__ out) {
    extern __shared__ float4 smem4[];
    float4* Wt = smem4;                 // [128][32] float4  (64 KB)
    float4* hs = smem4 + 128 * 32;      // [16][HSTRIDE] float4 (~33 KB)

    const int tid = threadIdx.x;
    const int mg = blockIdx.x >> 4;     // 0..7
    const int ng = blockIdx.x & 15;     // 0..15
    const int row0 = mg * 16;
    const int col0 = ng * 32;

    // One-time W^T load
    for (int i = tid; i < 128 * 32; i += 256) {
        int q = i >> 5;
        int c = i & 31;
        const float* wcol = Whh + (size_t)(4 * q) * HH + col0 + c;
        Wt[i] = make_float4(wcol[0], wcol[HH], wcol[2 * HH], wcol[3 * HH]);
    }

    const int warp = tid >> 5, lane = tid & 31;
    const int R = (warp >> 2) * 8 + (lane >> 2);   // 0..15 (row in tile)
    const int P = (warp & 3) * 4 + (lane & 3);     // 0..15 (col-pair)
    const int gr = row0 + R;
    const int c0 = 2 * P;
    const int gc = col0 + c0;

    unsigned* ctr = &g_ctr[mg * 32];
    volatile unsigned* gen = &g_gen[mg * 32];

    const ulonglong2* hp = (const ulonglong2*)(hs + R * HSTRIDE);
    const ulonglong2* wp = (const ulonglong2*)(Wt + c0);  // wp[q*32 + j] = Wt[q*32 + c0 + j]

    for (int t = 0; t < TT; t++) {
        const float* hin = g_h[t & 1];
        if (t > 0) {
            const float4* hin4 = (const float4*)hin + (size_t)row0 * (HH / 4);
#pragma unroll
            for (int qq = 0; qq < 8; qq++) {
                int idx = tid + qq * 256;
                int r = idx >> 7;           // 128 float4 per row
                int c4 = idx & 127;
                hs[r * HSTRIDE + c4] = __ldcg(hin4 + r * (HH / 4) + c4);
            }
        }
        __syncthreads();

        float2 xv = *(const float2*)&g_xp[((size_t)t * BB + gr) * HH + gc];

        float ax, ay;
        if (t > 0) {
            unsigned long long aA0 = 0ull, aB0 = 0ull, aA1 = 0ull, aB1 = 0ull;
#pragma unroll 4
            for (int q = 0; q < 128; q++) {
                ulonglong2 hv = hp[q];              // (h[4q],h[4q+1]),(h[4q+2],h[4q+3])
                ulonglong2 w0 = wp[q * 32];         // col c0, k-pairs (4q,4q+1),(4q+2,4q+3)
                ulonglong2 w1 = wp[q * 32 + 1];     // col c0+1
                aA0 = ffma2(hv.x, w0.x, aA0);
                aB0 = ffma2(hv.y, w0.y, aB0);
                aA1 = ffma2(hv.x, w1.x, aA1);
                aB1 = ffma2(hv.y, w1.y, aB1);
            }
            float s0, s1, s2, s3, s4, s5, s6, s7;
            unpack2(aA0, s0, s1);
            unpack2(aB0, s2, s3);
            unpack2(aA1, s4, s5);
            unpack2(aB1, s6, s7);
            ax = xv.x + ((s0 + s1) + (s2 + s3));
            ay = xv.y + ((s4 + s5) + (s6 + s7));
        } else {
            ax = xv.x;
            ay = xv.y;
        }
        float2 hv2;
        hv2.x = tanhf(ax);
        hv2.y = tanhf(ay);

        float* hout = g_h[(t + 1) & 1];
        *(float2*)&hout[(size_t)gr * HH + gc] = hv2;
        if (t == TT - 1) *(float2*)&out[(size_t)gr * HH + gc] = hv2;

        // ---- m-group barrier (16 CTAs) ----
        __threadfence();
        __syncthreads();
        if (tid == 0) {
            unsigned g = *gen;
            unsigned tk = atomicAdd(ctr, 1u);
            if (tk == 15u) {
                *(volatile unsigned*)ctr = 0u;
                __threadfence();
                atomicAdd((unsigned*)gen, 1u);
            } else {
                while (*gen == g) { }
            }
            __threadfence();
        }
        __syncthreads();
    }
}

// =====================================================================
extern "C" void kernel_launch(void* const* d_in, const int* in_sizes, int n_in,
                              void* d_out, int out_size) {
    const float* x    = (const float*)d_in[0];
    const float* Wih  = (const float*)d_in[1];
    const float* Whh  = (const float*)d_in[2];
    const float* bias = (const float*)d_in[3];
    float* out = (float*)d_out;

    const int smem2 = (128 * 32 + 16 * HSTRIDE) * (int)sizeof(float4);  // ~98.3 KB
    cudaFuncSetAttribute(rnn_steps_kernel,
                         cudaFuncAttributeMaxDynamicSharedMemorySize, smem2);

    dim3 g1(HH / 128, (BB * TT) / 128);   // (4, 1024)
    xp_gemm_kernel<<<g1, 256>>>(x, Wih, bias);
    rnn_steps_kernel<<<128, 256, smem2>>>(Whh, out);
}

// round 4
// speedup vs baseline: 1.0705x; 1.0428x over previous
#include <cuda_runtime.h>
#include <math.h>

#define BB 128
#define TT 1024
#define DD 512
#define HH 512

// ---------------- scratch ----------------
__device__ float g_xp[(size_t)TT * BB * HH];   // [t][b][h]
__device__ float g_h[2][BB * HH];              // ping-pong hidden state
__device__ unsigned g_ctr[8 * 32];
__device__ unsigned g_gen[8 * 32];

// ---------------- f32x2 helpers ----------------
__device__ __forceinline__ unsigned long long ffma2(unsigned long long a,
                                                    unsigned long long b,
                                                    unsigned long long c) {
    unsigned long long d;
    asm("fma.rn.f32x2 %0, %1, %2, %3;" : "=l"(d) : "l"(a), "l"(b), "l"(c));
    return d;
}
__device__ __forceinline__ unsigned long long add2(unsigned long long a,
                                                   unsigned long long b) {
    unsigned long long d;
    asm("add.rn.f32x2 %0, %1, %2;" : "=l"(d) : "l"(a), "l"(b));
    return d;
}
__device__ __forceinline__ unsigned long long pack2(float x, float y) {
    unsigned long long d;
    asm("mov.b64 %0, {%1, %2};" : "=l"(d) : "f"(x), "f"(y));
    return d;
}
__device__ __forceinline__ void unpack2(unsigned long long v, float& x, float& y) {
    asm("mov.b64 {%0, %1}, %2;" : "=f"(x), "=f"(y) : "l"(v));
}

// =====================================================================
// Phase 1: xp = x @ W_ih + b   (unchanged this round)
// =====================================================================
__global__ void __launch_bounds__(256) xp_gemm_kernel(
        const float* __restrict__ x, const float* __restrict__ Wih,
        const float* __restrict__ bias) {
    __shared__ float As[16][128];
    __shared__ float Bs[16][128];

    const int tid = threadIdx.x;
    const int tx = tid & 15;
    const int ty = tid >> 4;
    const int m0 = blockIdx.y * 128;
    const int n0 = blockIdx.x * 128;

    unsigned long long acc[8][4];
#pragma unroll
    for (int i = 0; i < 8; i++)
#pragma unroll
        for (int j = 0; j < 4; j++) acc[i][j] = 0ull;

    for (int k0 = 0; k0 < DD; k0 += 16) {
#pragma unroll
        for (int q = 0; q < 2; q++) {
            int i = tid + q * 256;
            int row = i >> 2;
            int kc = (i & 3) * 4;
            float4 av = *(const float4*)&x[(size_t)(m0 + row) * DD + k0 + kc];
            As[kc + 0][row] = av.x;
            As[kc + 1][row] = av.y;
            As[kc + 2][row] = av.z;
            As[kc + 3][row] = av.w;
        }
#pragma unroll
        for (int q = 0; q < 2; q++) {
            int i = tid + q * 256;
            int kr = i >> 5;
            int nc = (i & 31) * 4;
            float4 bv = *(const float4*)&Wih[(size_t)(k0 + kr) * HH + n0 + nc];
            *(float4*)&Bs[kr][nc] = bv;
        }
        __syncthreads();

#pragma unroll
        for (int kk = 0; kk < 16; kk++) {
            float4 a0 = *(const float4*)&As[kk][ty * 8];
            float4 a1 = *(const float4*)&As[kk][ty * 8 + 4];
            const unsigned long long* bp =
                (const unsigned long long*)&Bs[kk][tx * 8];
            unsigned long long b0 = bp[0], b1 = bp[1], b2 = bp[2], b3 = bp[3];
            float a[8] = {a0.x, a0.y, a0.z, a0.w, a1.x, a1.y, a1.z, a1.w};
#pragma unroll
            for (int i = 0; i < 8; i++) {
                unsigned long long ap = pack2(a[i], a[i]);
                acc[i][0] = ffma2(ap, b0, acc[i][0]);
                acc[i][1] = ffma2(ap, b1, acc[i][1]);
                acc[i][2] = ffma2(ap, b2, acc[i][2]);
                acc[i][3] = ffma2(ap, b3, acc[i][3]);
            }
        }
        __syncthreads();
    }

    float4 bv0 = *(const float4*)&bias[n0 + tx * 8];
    float4 bv1 = *(const float4*)&bias[n0 + tx * 8 + 4];
    float bb8[8] = {bv0.x, bv0.y, bv0.z, bv0.w, bv1.x, bv1.y, bv1.z, bv1.w};
#pragma unroll
    for (int i = 0; i < 8; i++) {
        int mrow = m0 + ty * 8 + i;
        int b_ = mrow >> 10;
        int t_ = mrow & 1023;
        float f[8];
        unpack2(acc[i][0], f[0], f[1]);
        unpack2(acc[i][1], f[2], f[3]);
        unpack2(acc[i][2], f[4], f[5]);
        unpack2(acc[i][3], f[6], f[7]);
#pragma unroll
        for (int j = 0; j < 8; j++) f[j] += bb8[j];
        float* dst = &g_xp[((size_t)t_ * BB + b_) * HH + n0 + tx * 8];
        *(float4*)&dst[0] = make_float4(f[0], f[1], f[2], f[3]);
        *(float4*)&dst[4] = make_float4(f[4], f[5], f[6], f[7]);
    }
}

// =====================================================================
// Phase 2 v3: register-resident W + k-split + warp reduce-scatter.
// 128 CTAs = 8 m-groups x 16 n-groups. CTA tile 16 rows x 32 cols,
// 256 threads. Thread (cg=warp, rh=lane>>4, kid=lane&15) owns
// W[kid*32..+31][cg*4..+3] in 64 f32x2 regs for the whole kernel.
// Only h flows through smem: 2048 crossbar cyc/step (was 12288).
// =====================================================================
#define HSF4 140   // float4 stride per smem h row (128 data + swizzle room)

__global__ void __launch_bounds__(256) rnn_steps_kernel(
        const float* __restrict__ Whh, float* __restrict__ out) {
    extern __shared__ float4 hs4[];                 // [16][HSF4]
    ulonglong2* hsU = (ulonglong2*)hs4;

    const int tid = threadIdx.x;
    const int warp = tid >> 5, lane = tid & 31;
    const int cg = warp;            // 0..7  (4 cols each)
    const int rh = lane >> 4;       // 0..1  (8 rows each)
    const int kid = lane & 15;      // 0..15 (32 k each)

    const int mg = blockIdx.x >> 4;
    const int ng = blockIdx.x & 15;
    const int row0 = mg * 16;
    const int col0 = ng * 32;

    // ---- one-time W load into registers: w[kk][c] = (W[k][col],W[k+1][col])
    unsigned long long w[16][4];
#pragma unroll
    for (int kk = 0; kk < 16; kk++) {
        int k = kid * 32 + 2 * kk;
        const float* p0 = Whh + (size_t)k * HH + col0 + cg * 4;
        const float* p1 = p0 + HH;
#pragma unroll
        for (int c = 0; c < 4; c++) w[kk][c] = pack2(p0[c], p1[c]);
    }

    // swizzled f4 base within h row for this thread's k-slice
    const int hoff = kid * 8 + ((kid >> 2) << 2);

    // output ownership after reduce-scatter: lane kid owns idx16 == kid
    const int grow = row0 + rh * 8 + (kid >> 1);
    const int gcol = col0 + cg * 4 + (kid & 1) * 2;

    unsigned* ctr = &g_ctr[mg * 32];
    volatile unsigned* gen = &g_gen[mg * 32];

    // ---------------- t = 0 (h = 0) ----------------
    {
        float2 xv = *(const float2*)&g_xp[(size_t)grow * HH + gcol];
        float2 hv2 = make_float2(tanhf(xv.x), tanhf(xv.y));
        *(float2*)&g_h[1][(size_t)grow * HH + gcol] = hv2;
        __threadfence();
        __syncthreads();
        if (tid == 0) {
            unsigned g = *gen;
            unsigned tk = atomicAdd(ctr, 1u);
            if (tk == 15u) {
                *(volatile unsigned*)ctr = 0u;
                __threadfence();
                atomicAdd((unsigned*)gen, 1u);
            } else {
                while (*gen == g) { }
            }
            __threadfence();
        }
        __syncthreads();
    }

    // ---------------- t = 1 .. TT-1 ----------------
    for (int t = 1; t < TT; t++) {
        // prefetch xp early (DRAM latency hidden behind compute)
        float2 xv = __ldcg((const float2*)&g_xp[((size_t)t * BB + grow) * HH + gcol]);

        // cooperative swizzled load of this group's 16 h rows
        const float4* hin4 = (const float4*)g_h[t & 1] + (size_t)row0 * (HH / 4);
#pragma unroll
        for (int qq = 0; qq < 8; qq++) {
            int idx = tid + qq * 256;
            int r = idx >> 7;
            int c4 = idx & 127;
            int pos = c4 + ((c4 >> 5) << 2);
            hs4[r * HSF4 + pos] = __ldcg(hin4 + r * 128 + c4);
        }
        __syncthreads();

        // ---- compute partials: acc[idx16][slot], idx16 = ri*2 + (c>>1)
        unsigned long long acc[16][2];
#pragma unroll
        for (int i = 0; i < 16; i++) { acc[i][0] = 0ull; acc[i][1] = 0ull; }

#pragma unroll
        for (int ri = 0; ri < 8; ri++) {
            const ulonglong2* hp = hsU + (rh * 8 + ri) * HSF4 + hoff;
#pragma unroll
            for (int j = 0; j < 8; j++) {
                ulonglong2 hv = hp[j];   // k-pairs (4j,4j+1),(4j+2,4j+3) of this k-slice
                int kk = 2 * j;
                acc[ri * 2 + 0][0] = ffma2(hv.x, w[kk][0], acc[ri * 2 + 0][0]);
                acc[ri * 2 + 0][1] = ffma2(hv.x, w[kk][1], acc[ri * 2 + 0][1]);
                acc[ri * 2 + 1][0] = ffma2(hv.x, w[kk][2], acc[ri * 2 + 1][0]);
                acc[ri * 2 + 1][1] = ffma2(hv.x, w[kk][3], acc[ri * 2 + 1][1]);
                acc[ri * 2 + 0][0] = ffma2(hv.y, w[kk + 1][0], acc[ri * 2 + 0][0]);
                acc[ri * 2 + 0][1] = ffma2(hv.y, w[kk + 1][1], acc[ri * 2 + 0][1]);
                acc[ri * 2 + 1][0] = ffma2(hv.y, w[kk + 1][2], acc[ri * 2 + 1][0]);
                acc[ri * 2 + 1][1] = ffma2(hv.y, w[kk + 1][3], acc[ri * 2 + 1][1]);
            }
        }

        // ---- reduce-scatter over the 16 kid lanes (masks 8,4,2,1)
#pragma unroll
        for (int rnd = 0; rnd < 4; rnd++) {
            const int m = 8 >> rnd;
            const int half = 8 >> rnd;
            const bool up = (kid & m) != 0;
#pragma unroll
            for (int i = 0; i < 8; i++) {
                if (i < half) {
                    unsigned long long g0 = up ? acc[i][0] : acc[i + half][0];
                    unsigned long long g1 = up ? acc[i][1] : acc[i + half][1];
                    unsigned long long r0 = __shfl_xor_sync(0xffffffffu, g0, m);
                    unsigned long long r1 = __shfl_xor_sync(0xffffffffu, g1, m);
                    unsigned long long k0 = up ? acc[i + half][0] : acc[i][0];
                    unsigned long long k1 = up ? acc[i + half][1] : acc[i][1];
                    acc[i][0] = add2(k0, r0);
                    acc[i][1] = add2(k1, r1);
                }
            }
        }

        // ---- epilogue: fold (even,odd), add xp, tanh, store
        float a, b;
        unpack2(acc[0][0], a, b);
        float s0 = a + b;
        unpack2(acc[0][1], a, b);
        float s1 = a + b;
        float2 hv2 = make_float2(tanhf(xv.x + s0), tanhf(xv.y + s1));

        float* hout = g_h[(t + 1) & 1];
        *(float2*)&hout[(size_t)grow * HH + gcol] = hv2;
        if (t == TT - 1) *(float2*)&out[(size_t)grow * HH + gcol] = hv2;

        // ---- m-group barrier (16 CTAs) ----
        __threadfence();
        __syncthreads();
        if (tid == 0) {
            unsigned g = *gen;
            unsigned tk = atomicAdd(ctr, 1u);
            if (tk == 15u) {
                *(volatile unsigned*)ctr = 0u;
                __threadfence();
                atomicAdd((unsigned*)gen, 1u);
            } else {
                while (*gen == g) { }
            }
            __threadfence();
        }
        __syncthreads();
    }
}

// =====================================================================
extern "C" void kernel_launch(void* const* d_in, const int* in_sizes, int n_in,
                              void* d_out, int out_size) {
    const float* x    = (const float*)d_in[0];
    const float* Wih  = (const float*)d_in[1];
    const float* Whh  = (const float*)d_in[2];
    const float* bias = (const float*)d_in[3];
    float* out = (float*)d_out;

    const int smem2 = 16 * HSF4 * (int)sizeof(float4);   // 35840 B
    cudaFuncSetAttribute(rnn_steps_kernel,
                         cudaFuncAttributeMaxDynamicSharedMemorySize, smem2);

    dim3 g1(HH / 128, (BB * TT) / 128);   // (4, 1024)
    xp_gemm_kernel<<<g1, 256>>>(x, Wih, bias);
    rnn_steps_kernel<<<128, 256, smem2>>>(Whh, out);
}

// round 7
// speedup vs baseline: 1.5720x; 1.4686x over previous
#include <cuda_runtime.h>
#include <math.h>

#define BB 128
#define TT 1024
#define DD 512
#define HH 512

// ---------------- scratch ----------------
__device__ float g_xp[(size_t)TT * BB * HH];   // [t][b][h]
__device__ float g_h[2][BB * HH];              // ping-pong hidden state
__device__ unsigned g_ctr[8 * 32];
__device__ unsigned g_gen[8 * 32];

// ---------------- f32x2 helpers ----------------
__device__ __forceinline__ unsigned long long ffma2(unsigned long long a,
                                                    unsigned long long b,
                                                    unsigned long long c) {
    unsigned long long d;
    asm("fma.rn.f32x2 %0, %1, %2, %3;" : "=l"(d) : "l"(a), "l"(b), "l"(c));
    return d;
}
__device__ __forceinline__ unsigned long long add2(unsigned long long a,
                                                   unsigned long long b) {
    unsigned long long d;
    asm("add.rn.f32x2 %0, %1, %2;" : "=l"(d) : "l"(a), "l"(b));
    return d;
}
__device__ __forceinline__ unsigned long long pack2(float x, float y) {
    unsigned long long d;
    asm("mov.b64 %0, {%1, %2};" : "=l"(d) : "f"(x), "f"(y));
    return d;
}
__device__ __forceinline__ void unpack2(unsigned long long v, float& x, float& y) {
    asm("mov.b64 {%0, %1}, %2;" : "=f"(x), "=f"(y) : "l"(v));
}

// =====================================================================
// Phase 1: xp = x @ W_ih + b   (unchanged)
// =====================================================================
__global__ void __launch_bounds__(256) xp_gemm_kernel(
        const float* __restrict__ x, const float* __restrict__ Wih,
        const float* __restrict__ bias) {
    __shared__ float As[16][128];
    __shared__ float Bs[16][128];

    const int tid = threadIdx.x;
    const int tx = tid & 15;
    const int ty = tid >> 4;
    const int m0 = blockIdx.y * 128;
    const int n0 = blockIdx.x * 128;

    unsigned long long acc[8][4];
#pragma unroll
    for (int i = 0; i < 8; i++)
#pragma unroll
        for (int j = 0; j < 4; j++) acc[i][j] = 0ull;

    for (int k0 = 0; k0 < DD; k0 += 16) {
#pragma unroll
        for (int q = 0; q < 2; q++) {
            int i = tid + q * 256;
            int row = i >> 2;
            int kc = (i & 3) * 4;
            float4 av = *(const float4*)&x[(size_t)(m0 + row) * DD + k0 + kc];
            As[kc + 0][row] = av.x;
            As[kc + 1][row] = av.y;
            As[kc + 2][row] = av.z;
            As[kc + 3][row] = av.w;
        }
#pragma unroll
        for (int q = 0; q < 2; q++) {
            int i = tid + q * 256;
            int kr = i >> 5;
            int nc = (i & 31) * 4;
            float4 bv = *(const float4*)&Wih[(size_t)(k0 + kr) * HH + n0 + nc];
            *(float4*)&Bs[kr][nc] = bv;
        }
        __syncthreads();

#pragma unroll
        for (int kk = 0; kk < 16; kk++) {
            float4 a0 = *(const float4*)&As[kk][ty * 8];
            float4 a1 = *(const float4*)&As[kk][ty * 8 + 4];
            const unsigned long long* bp =
                (const unsigned long long*)&Bs[kk][tx * 8];
            unsigned long long b0 = bp[0], b1 = bp[1], b2 = bp[2], b3 = bp[3];
            float a[8] = {a0.x, a0.y, a0.z, a0.w, a1.x, a1.y, a1.z, a1.w};
#pragma unroll
            for (int i = 0; i < 8; i++) {
                unsigned long long ap = pack2(a[i], a[i]);
                acc[i][0] = ffma2(ap, b0, acc[i][0]);
                acc[i][1] = ffma2(ap, b1, acc[i][1]);
                acc[i][2] = ffma2(ap, b2, acc[i][2]);
                acc[i][3] = ffma2(ap, b3, acc[i][3]);
            }
        }
        __syncthreads();
    }

    float4 bv0 = *(const float4*)&bias[n0 + tx * 8];
    float4 bv1 = *(const float4*)&bias[n0 + tx * 8 + 4];
    float bb8[8] = {bv0.x, bv0.y, bv0.z, bv0.w, bv1.x, bv1.y, bv1.z, bv1.w};
#pragma unroll
    for (int i = 0; i < 8; i++) {
        int mrow = m0 + ty * 8 + i;
        int b_ = mrow >> 10;
        int t_ = mrow & 1023;
        float f[8];
        unpack2(acc[i][0], f[0], f[1]);
        unpack2(acc[i][1], f[2], f[3]);
        unpack2(acc[i][2], f[4], f[5]);
        unpack2(acc[i][3], f[6], f[7]);
#pragma unroll
        for (int j = 0; j < 8; j++) f[j] += bb8[j];
        float* dst = &g_xp[((size_t)t_ * BB + b_) * HH + n0 + tx * 8];
        *(float4*)&dst[0] = make_float4(f[0], f[1], f[2], f[3]);
        *(float4*)&dst[4] = make_float4(f[4], f[5], f[6], f[7]);
    }
}

// =====================================================================
// Phase 2 v5: register-resident W, k-split 16, warp reduce-scatter,
// XOR bank swizzle on the h tile.
//   store: pos = c4 ^ ((c4>>3)&7)           (involution, key = c4>>3 & 7)
//   read : hp[j ^ kx] at base kid*8 holds LOGICAL quad j  -> pair with w[2*j]
// (R5 bug was pairing with w[2*(j^kx)] — double un-swizzle.)
// =====================================================================
#define HSF4 140   // float4 stride per smem h row

__global__ void __launch_bounds__(256) rnn_steps_kernel(
        const float* __restrict__ Whh, float* __restrict__ out) {
    extern __shared__ float4 hs4[];                 // [16][HSF4]
    ulonglong2* hsU = (ulonglong2*)hs4;

    const int tid = threadIdx.x;
    const int warp = tid >> 5, lane = tid & 31;
    const int cg = warp;            // 0..7  (4 cols each)
    const int rh = lane >> 4;       // 0..1  (8 rows each)
    const int kid = lane & 15;      // 0..15 (32 k each)
    const int kx = kid & 7;         // XOR key for swizzled reads

    const int mg = blockIdx.x >> 4;
    const int ng = blockIdx.x & 15;
    const int row0 = mg * 16;
    const int col0 = ng * 32;

    // ---- one-time W load: w[kk][c] = (W[k][col], W[k+1][col])
    unsigned long long w[16][4];
#pragma unroll
    for (int kk = 0; kk < 16; kk++) {
        int k = kid * 32 + 2 * kk;
        const float* p0 = Whh + (size_t)k * HH + col0 + cg * 4;
        const float* p1 = p0 + HH;
#pragma unroll
        for (int c = 0; c < 4; c++) w[kk][c] = pack2(p0[c], p1[c]);
    }

    // output ownership after reduce-scatter: lane kid owns idx16 == kid
    const int grow = row0 + rh * 8 + (kid >> 1);
    const int gcol = col0 + cg * 4 + (kid & 1) * 2;

    unsigned* ctr = &g_ctr[mg * 32];
    volatile unsigned* gen = &g_gen[mg * 32];

    // ---------------- t = 0 (h = 0) ----------------
    {
        float2 xv = *(const float2*)&g_xp[(size_t)grow * HH + gcol];
        float2 hv2 = make_float2(tanhf(xv.x), tanhf(xv.y));
        *(float2*)&g_h[1][(size_t)grow * HH + gcol] = hv2;
        __threadfence();
        __syncthreads();
        if (tid == 0) {
            unsigned g = *gen;
            unsigned tk = atomicAdd(ctr, 1u);
            if (tk == 15u) {
                *(volatile unsigned*)ctr = 0u;
                __threadfence();
                atomicAdd((unsigned*)gen, 1u);
            } else {
                while (*gen == g) { }
            }
            __threadfence();
        }
        __syncthreads();
    }

    // ---------------- t = 1 .. TT-1 ----------------
    for (int t = 1; t < TT; t++) {
        float2 xv = __ldcg((const float2*)&g_xp[((size_t)t * BB + grow) * HH + gcol]);

        // cooperative swizzled load of this group's 16 h rows
        const float4* hin4 = (const float4*)g_h[t & 1] + (size_t)row0 * (HH / 4);
#pragma unroll
        for (int qq = 0; qq < 8; qq++) {
            int idx = tid + qq * 256;
            int r = idx >> 7;
            int c4 = idx & 127;
            int pos = c4 ^ ((c4 >> 3) & 7);
            hs4[r * HSF4 + pos] = __ldcg(hin4 + r * 128 + c4);
        }
        __syncthreads();

        // ---- compute partials: acc[idx16][slot], idx16 = ri*2 + (c>>1)
        unsigned long long acc[16][2];
#pragma unroll
        for (int i = 0; i < 16; i++) { acc[i][0] = 0ull; acc[i][1] = 0ull; }

#pragma unroll
        for (int ri = 0; ri < 8; ri++) {
            const ulonglong2* hp = hsU + (rh * 8 + ri) * HSF4 + kid * 8;
#pragma unroll
            for (int j = 0; j < 8; j++) {
                ulonglong2 hv = hp[j ^ kx];   // physical j^kx == logical quad j
                int kk = 2 * j;               // pair with W quad j (FIXED)
                acc[ri * 2 + 0][0] = ffma2(hv.x, w[kk][0], acc[ri * 2 + 0][0]);
                acc[ri * 2 + 0][1] = ffma2(hv.x, w[kk][1], acc[ri * 2 + 0][1]);
                acc[ri * 2 + 1][0] = ffma2(hv.x, w[kk][2], acc[ri * 2 + 1][0]);
                acc[ri * 2 + 1][1] = ffma2(hv.x, w[kk][3], acc[ri * 2 + 1][1]);
                acc[ri * 2 + 0][0] = ffma2(hv.y, w[kk + 1][0], acc[ri * 2 + 0][0]);
                acc[ri * 2 + 0][1] = ffma2(hv.y, w[kk + 1][1], acc[ri * 2 + 0][1]);
                acc[ri * 2 + 1][0] = ffma2(hv.y, w[kk + 1][2], acc[ri * 2 + 1][0]);
                acc[ri * 2 + 1][1] = ffma2(hv.y, w[kk + 1][3], acc[ri * 2 + 1][1]);
            }
        }

        // ---- reduce-scatter over the 16 kid lanes (masks 8,4,2,1)
#pragma unroll
        for (int rnd = 0; rnd < 4; rnd++) {
            const int m = 8 >> rnd;
            const int half = 8 >> rnd;
            const bool up = (kid & m) != 0;
#pragma unroll
            for (int i = 0; i < 8; i++) {
                if (i < half) {
                    unsigned long long g0 = up ? acc[i][0] : acc[i + half][0];
                    unsigned long long g1 = up ? acc[i][1] : acc[i + half][1];
                    unsigned long long r0 = __shfl_xor_sync(0xffffffffu, g0, m);
                    unsigned long long r1 = __shfl_xor_sync(0xffffffffu, g1, m);
                    unsigned long long k0 = up ? acc[i + half][0] : acc[i][0];
                    unsigned long long k1 = up ? acc[i + half][1] : acc[i][1];
                    acc[i][0] = add2(k0, r0);
                    acc[i][1] = add2(k1, r1);
                }
            }
        }

        // ---- epilogue
        float a, b;
        unpack2(acc[0][0], a, b);
        float s0 = a + b;
        unpack2(acc[0][1], a, b);
        float s1 = a + b;
        float2 hv2 = make_float2(tanhf(xv.x + s0), tanhf(xv.y + s1));

        float* hout = g_h[(t + 1) & 1];
        *(float2*)&hout[(size_t)grow * HH + gcol] = hv2;
        if (t == TT - 1) *(float2*)&out[(size_t)grow * HH + gcol] = hv2;

        // ---- m-group barrier (16 CTAs) ----
        __threadfence();
        __syncthreads();
        if (tid == 0) {
            unsigned g = *gen;
            unsigned tk = atomicAdd(ctr, 1u);
            if (tk == 15u) {
                *(volatile unsigned*)ctr = 0u;
                __threadfence();
                atomicAdd((unsigned*)gen, 1u);
            } else {
                while (*gen == g) { }
            }
            __threadfence();
        }
        __syncthreads();
    }
}

// =====================================================================
extern "C" void kernel_launch(void* const* d_in, const int* in_sizes, int n_in,
                              void* d_out, int out_size) {
    const float* x    = (const float*)d_in[0];
    const float* Wih  = (const float*)d_in[1];
    const float* Whh  = (const float*)d_in[2];
    const float* bias = (const float*)d_in[3];
    float* out = (float*)d_out;

    const int smem2 = 16 * HSF4 * (int)sizeof(float4);   // 35840 B
    cudaFuncSetAttribute(rnn_steps_kernel,
                         cudaFuncAttributeMaxDynamicSharedMemorySize, smem2);

    dim3 g1(HH / 128, (BB * TT) / 128);   // (4, 1024)
    xp_gemm_kernel<<<g1, 256>>>(x, Wih, bias);
    rnn_steps_kernel<<<128, 256, smem2>>>(Whh, out);
}